// round 17
// baseline (speedup 1.0000x reference)
#include <cuda_runtime.h>
#include <cuda_fp16.h>
#include <math.h>
#include <stdint.h>

#define NN    8192
#define INDIM 1024
#define DD    512
#define DHALF 256

// ------------------------- scratch (device globals) -------------------------
__device__ __half g_xh[NN * INDIM];             // fp16 x
__device__ __half g_wqkvT[1536 * INDIM];        // [n][k] packed [Wq|Wk|Wv]^T
__device__ float  g_bqkv[1536];
__device__ __half g_w1T[DHALF * DD];            // W1^T [256][512]
__device__ __half g_qkvh[NN * 1536];            // q|k|v fp16 (ld=1536)
__device__ __half g_vpT[DHALF * NN];            // (V @ W1)^T  [256][8192]
__device__ __half g_eh[(size_t)NN * NN];        // E = exp(S/sqrt(D)) fp16
__device__ float  g_r[NN];                      // row sums of E (atomic)
__device__ float  g_u[8 * (size_t)NN * DHALF];  // split-K partials of E @ V'

// exp via exp2 range reduction, pure FMA/ALU (avoids MUFU serialization)
__device__ __forceinline__ float fast_exp(float x) {
    float y = x * 1.44269504088896f;
    float i = rintf(y);
    float t = (y - i) * 0.69314718055995f;
    float p = 1.3888889e-3f;
    p = fmaf(p, t, 8.3333333e-3f);
    p = fmaf(p, t, 4.1666667e-2f);
    p = fmaf(p, t, 1.6666667e-1f);
    p = fmaf(p, t, 0.5f);
    p = fmaf(p, t, 1.0f);
    p = fmaf(p, t, 1.0f);
    return p * __int_as_float(((int)i + 127) << 23);
}

__device__ __forceinline__ void mma16(float* d, const unsigned* a, const unsigned* b) {
    asm volatile(
        "mma.sync.aligned.m16n8k16.row.col.f32.f16.f16.f32 "
        "{%0,%1,%2,%3}, {%4,%5,%6,%7}, {%8,%9}, {%0,%1,%2,%3};\n"
        : "+f"(d[0]), "+f"(d[1]), "+f"(d[2]), "+f"(d[3])
        : "r"(a[0]), "r"(a[1]), "r"(a[2]), "r"(a[3]), "r"(b[0]), "r"(b[1]));
}

__device__ __forceinline__ void ldm4(unsigned* r, uint32_t addr) {
    asm volatile(
        "ldmatrix.sync.aligned.m8n8.x4.shared.b16 {%0,%1,%2,%3}, [%4];\n"
        : "=r"(r[0]), "=r"(r[1]), "=r"(r[2]), "=r"(r[3]) : "r"(addr));
}

__device__ __forceinline__ void cpa16s(uint32_t dst, const __half* src) {
    asm volatile("cp.async.cg.shared.global [%0], [%1], 16;\n" :: "r"(dst), "l"(src));
}

// ---- mbarrier machinery (async pipeline, per-warp drift) -------------------
#define MBAR_INIT(a, n) \
    asm volatile("mbarrier.init.shared.b64 [%0], %1;" :: "r"(a), "r"(n) : "memory")
#define MBAR_ARRIVE(a) \
    asm volatile("mbarrier.arrive.shared.b64 _, [%0];" :: "r"(a) : "memory")
// .noinc: async completion arrives AGAINST the initialized expected count
#define CPA_MBAR_ARRIVE(a) \
    asm volatile("cp.async.mbarrier.arrive.noinc.shared.b64 [%0];" :: "r"(a) : "memory")
#define MBAR_WAIT(mbar, parity) do {                                           \
    uint32_t _m = (mbar); uint32_t _p = (parity); uint32_t _done;              \
    asm volatile("{\n\t.reg .pred P;\n\t"                                      \
        "mbarrier.try_wait.parity.acquire.cta.shared::cta.b64 P, [%1], %2;\n\t"\
        "selp.b32 %0, 1, 0, P;\n\t}"                                           \
        : "=r"(_done) : "r"(_m), "r"(_p) : "memory");                          \
    while (!_done) {                                                           \
        asm volatile("{\n\t.reg .pred P;\n\t"                                  \
            "mbarrier.try_wait.parity.acquire.cta.shared::cta.b64 P, [%1], %2, 0x989680;\n\t" \
            "selp.b32 %0, 1, 0, P;\n\t}"                                       \
            : "=r"(_done) : "r"(_m), "r"(_p) : "memory");                      \
    }                                                                          \
} while (0)

// ---------------------------------------------------------------------------
// fp16 mma.sync GEMM, 3-stage cp.async pipeline tracked by mbarrier pairs.
// NO __syncthreads in the mainloop. Block tile 128x128, kTile 64,
// 128 threads = 4 warps (2 x 2), warp tile 64x64 (MAC/byte = 16.4, beats
// the ~14 smem-crossbar break-even). __launch_bounds__(128,2) -> 2 CTAs/SM:
// cross-CTA interleave + warp drift cover frag-load latency.
//   C[M x Nc] = f(A[M x K] @ B^T), A row-major [m][k], B row-major [n][k].
//   EPI: 0 = half(acc + bias)            (C half, ld ldc)
//        1 = half(fast_exp(acc*scale))   (C half) + atomic row-sum into g_r
//        2 = float acc                   (C float, split-K plane z*c_split)
//        3 = half(acc), TRANSPOSED store C'[n][m] ld NN
// ---------------------------------------------------------------------------
#define NTHR     128
#define KT       64
#define ROWB     144                     // smem row stride bytes (64 halfs + 8 pad)
#define A_STG_B  (128 * ROWB)            // 18432
#define B_STG_B  (128 * ROWB)            // 18432
#define STG_B    (A_STG_B + B_STG_B)     // 36864
#define NSTAGE   3
#define MBAR_SP  128                     // mbar region at smem start
#define SMEM_BYTES (MBAR_SP + NSTAGE * STG_B)   // 110720/CTA (x2 = 221440)
static_assert(2 * SMEM_BYTES <= 227 * 1024, "smem");

template<int EPI>
__global__ __launch_bounds__(NTHR, 2) void gemm_h(
    const __half* __restrict__ A, int lda,
    const __half* __restrict__ B, int ldb,
    void* __restrict__ Cv, int ldc, size_t c_split,
    int Kchunk, const float* __restrict__ bias, float scale)
{
    extern __shared__ char smem[];
    const uint32_t sb = (uint32_t)__cvta_generic_to_shared(smem);
    const uint32_t mb_full  = sb;        // full[s] at sb + 8*s
    const uint32_t mb_empty = sb + 24;   // empty[s] at sb + 24 + 8*s

    const int tid  = threadIdx.x;
    const int lane = tid & 31;
    const int warp = tid >> 5;
    const int wm   = warp >> 1;          // 0..1  (64 rows each)
    const int wn   = warp & 1;           // 0..1  (64 cols each)
    const int gid  = lane >> 2;          // epilogue row
    const int tig  = lane & 3;           // epilogue col pair
    const int g8   = lane >> 3;          // ldmatrix address group 0..3
    const int lr   = lane & 7;
    const int rb   = blockIdx.y * 128;
    const int cb   = blockIdx.x * 128;
    const int kbase = blockIdx.z * Kchunk;

    if (tid == 0) {
#pragma unroll
        for (int s = 0; s < NSTAGE; s++) {
            MBAR_INIT(mb_full + 8 * s, NTHR);
            MBAR_INIT(mb_empty + 8 * s, NTHR);
        }
    }
    __syncthreads();   // mbars visible before any arrive/wait

    // ldmatrix per-lane byte offsets (within a stage's A / B region)
    const uint32_t a_lm = (uint32_t)(wm * 64 + (g8 & 1) * 8 + lr) * ROWB
                        + (uint32_t)(g8 >> 1) * 16;
    const uint32_t b_lm = (uint32_t)(wn * 64 + (g8 >> 1) * 8 + lr) * ROWB
                        + (uint32_t)(g8 & 1) * 16;

    float acc[4][8][4];
#pragma unroll
    for (int mt = 0; mt < 4; mt++)
#pragma unroll
        for (int nt = 0; nt < 8; nt++)
#pragma unroll
            for (int i = 0; i < 4; i++) acc[mt][nt][i] = 0.f;

    auto issueLoads = [&](int slot, int k0) {
        uint32_t ab = sb + MBAR_SP + slot * STG_B;
        uint32_t bb = ab + A_STG_B;
#pragma unroll
        for (int i = 0; i < 8; i++) {    // A: 128 rows x 8 chunks of 16B
            int q = tid + i * NTHR;
            int r = q >> 3, c = q & 7;
            cpa16s(ab + r * ROWB + c * 16,
                   &A[(size_t)(rb + r) * lda + kbase + k0 + c * 8]);
        }
#pragma unroll
        for (int i = 0; i < 8; i++) {    // B: 128 n-rows x 8 chunks of 16B
            int q = tid + i * NTHR;
            int r = q >> 3, c = q & 7;
            cpa16s(bb + r * ROWB + c * 16,
                   &B[(size_t)(cb + r) * ldb + kbase + k0 + c * 8]);
        }
    };

    const int NIT = Kchunk / KT;
    issueLoads(0, 0);   CPA_MBAR_ARRIVE(mb_full + 0);
    issueLoads(1, KT);  CPA_MBAR_ARRIVE(mb_full + 8);

    int fslot = 0, fphase = 0;           // consumer cursor over full[]

    for (int j = 0; j < NIT; ++j) {
        MBAR_WAIT(mb_full + 8 * fslot, fphase);

        const uint32_t abase = sb + MBAR_SP + fslot * STG_B;
        const uint32_t bbase = abase + A_STG_B;

#pragma unroll
        for (int ko = 0; ko < 4; ko++) {  // four k16 steps per 64-wide tile
            unsigned af[4][4], bf[8][2];
#pragma unroll
            for (int mt = 0; mt < 4; mt++)
                ldm4(af[mt], abase + a_lm + mt * 16 * ROWB + ko * 32);
#pragma unroll
            for (int p = 0; p < 4; p++) {  // nt pairs (2p, 2p+1)
                unsigned r[4];
                ldm4(r, bbase + b_lm + p * 16 * ROWB + ko * 32);
                bf[2 * p][0] = r[0];      bf[2 * p][1] = r[1];
                bf[2 * p + 1][0] = r[2];  bf[2 * p + 1][1] = r[3];
            }
            if (ko == 3) MBAR_ARRIVE(mb_empty + 8 * fslot);  // all frags read
#pragma unroll
            for (int mt = 0; mt < 4; mt++)
#pragma unroll
                for (int nt = 0; nt < 8; nt++)
                    mma16(acc[mt][nt], af[mt], bf[nt]);
        }

        // producer duty: refill stage j+2
        int nx = j + 2;
        if (nx < NIT) {
            int ns = nx % NSTAGE;
            if (nx >= NSTAGE)            // first write of each slot needs no wait
                MBAR_WAIT(mb_empty + 8 * ns, ((nx - NSTAGE) / NSTAGE) & 1);
            issueLoads(ns, nx * KT);
            CPA_MBAR_ARRIVE(mb_full + 8 * ns);
        }

        if (++fslot == NSTAGE) { fslot = 0; fphase ^= 1; }
    }

    // ----- epilogue -----
    float rs[4][2];
    if (EPI == 1) {
#pragma unroll
        for (int mt = 0; mt < 4; mt++) { rs[mt][0] = 0.f; rs[mt][1] = 0.f; }
    }
#pragma unroll
    for (int mt = 0; mt < 4; mt++) {
#pragma unroll
        for (int nt = 0; nt < 8; nt++) {
            int r0 = rb + wm * 64 + mt * 16 + gid;
            int c0 = cb + wn * 64 + nt * 8 + 2 * tig;
            float v0 = acc[mt][nt][0], v1 = acc[mt][nt][1];
            float v2 = acc[mt][nt][2], v3 = acc[mt][nt][3];
            if (EPI == 0) {
                __half* C = (__half*)Cv;
                float b0 = bias[c0], b1v = bias[c0 + 1];
                *(__half2*)&C[(size_t)r0 * ldc + c0] =
                    __floats2half2_rn(v0 + b0, v1 + b1v);
                *(__half2*)&C[(size_t)(r0 + 8) * ldc + c0] =
                    __floats2half2_rn(v2 + b0, v3 + b1v);
            } else if (EPI == 1) {
                __half* C = (__half*)Cv;
                float e0 = fast_exp(v0 * scale), e1 = fast_exp(v1 * scale);
                float e2 = fast_exp(v2 * scale), e3 = fast_exp(v3 * scale);
                *(__half2*)&C[(size_t)r0 * ldc + c0]       = __floats2half2_rn(e0, e1);
                *(__half2*)&C[(size_t)(r0 + 8) * ldc + c0] = __floats2half2_rn(e2, e3);
                rs[mt][0] += e0 + e1;
                rs[mt][1] += e2 + e3;
            } else if (EPI == 2) {
                float* C = (float*)Cv + blockIdx.z * c_split;
                *(float2*)&C[(size_t)r0 * ldc + c0]       = make_float2(v0, v1);
                *(float2*)&C[(size_t)(r0 + 8) * ldc + c0] = make_float2(v2, v3);
            } else {  // EPI 3: transposed half store C'[n][m], ld NN
                __half* C = (__half*)Cv;
                C[(size_t)c0 * NN + r0]           = __float2half_rn(v0);
                C[(size_t)(c0 + 1) * NN + r0]     = __float2half_rn(v1);
                C[(size_t)c0 * NN + r0 + 8]       = __float2half_rn(v2);
                C[(size_t)(c0 + 1) * NN + r0 + 8] = __float2half_rn(v3);
            }
        }
    }
    if (EPI == 1) {
#pragma unroll
        for (int mt = 0; mt < 4; mt++) {
            float s0 = rs[mt][0], s1 = rs[mt][1];
            s0 += __shfl_xor_sync(0xffffffffu, s0, 1);
            s0 += __shfl_xor_sync(0xffffffffu, s0, 2);
            s1 += __shfl_xor_sync(0xffffffffu, s1, 1);
            s1 += __shfl_xor_sync(0xffffffffu, s1, 2);
            if (tig == 0) {
                int r0 = rb + wm * 64 + mt * 16 + gid;
                atomicAdd(&g_r[r0], s0);
                atomicAdd(&g_r[r0 + 8], s1);
            }
        }
    }
}

// --------------------------- prep / aux kernels -----------------------------
__global__ void xprep_h(const float* __restrict__ x, __half* __restrict__ o, int n4)
{
    int i = blockIdx.x * blockDim.x + threadIdx.x;
    if (i < n4) {
        float4 v = ((const float4*)x)[i];
        __half2* o2 = (__half2*)o;
        o2[i * 2]     = __floats2half2_rn(v.x, v.y);
        o2[i * 2 + 1] = __floats2half2_rn(v.z, v.w);
    }
}

__global__ void pack_wqkvT(const float* __restrict__ Wq, const float* __restrict__ Wk,
                           const float* __restrict__ Wv,
                           const float* __restrict__ bq, const float* __restrict__ bk,
                           const float* __restrict__ bv)
{
    int i = blockIdx.x * blockDim.x + threadIdx.x;
    if (i < 1536 * INDIM) {
        int c = i / INDIM, r = i % INDIM;
        float v = (c < 512) ? Wq[r * 512 + c]
               : (c < 1024) ? Wk[r * 512 + c - 512]
                            : Wv[r * 512 + c - 1024];
        g_wqkvT[i] = __float2half_rn(v);
    }
    if (i < 1536)
        g_bqkv[i] = (i < 512) ? bq[i] : (i < 1024) ? bk[i - 512] : bv[i - 1024];
}

// also zeroes g_r
__global__ void pack_w1T(const float* __restrict__ W1)
{
    int i = blockIdx.x * blockDim.x + threadIdx.x;
    if (i < DHALF * DD) {
        int n = i / DD, k = i % DD;
        g_w1T[i] = __float2half_rn(W1[k * DHALF + n]);
    }
    if (i < NN) g_r[i] = 0.f;
}

__global__ __launch_bounds__(256) void pv_reduce_score(
    const float* __restrict__ b1, const float* __restrict__ W2,
    const float* __restrict__ b2, float* __restrict__ out)
{
    const int row = blockIdx.x;
    const int t = threadIdx.x;
    __shared__ float red[256];
    float s = 0.f;
#pragma unroll
    for (int z = 0; z < 8; z++)
        s += g_u[(size_t)z * NN * DHALF + (size_t)row * DHALF + t];
    float h = fmaxf(s / g_r[row] + b1[t], 0.f);
    red[t] = h * W2[t];
    __syncthreads();
    for (int w = 128; w > 0; w >>= 1) {
        if (t < w) red[t] += red[t + w];
        __syncthreads();
    }
    if (t == 0) out[row] = red[0] + b2[0];
}

// ---------------------------------------------------------------------------
extern "C" void kernel_launch(void* const* d_in, const int* in_sizes, int n_in,
                              void* d_out, int out_size)
{
    const float* x  = (const float*)d_in[0];
    const float* Wq = (const float*)d_in[1];
    const float* bq = (const float*)d_in[2];
    const float* Wk = (const float*)d_in[3];
    const float* bk = (const float*)d_in[4];
    const float* Wv = (const float*)d_in[5];
    const float* bv = (const float*)d_in[6];
    const float* W1 = (const float*)d_in[7];
    const float* b1 = (const float*)d_in[8];
    const float* W2 = (const float*)d_in[9];
    const float* b2 = (const float*)d_in[10];
    float* out = (float*)d_out;

    __half *pxh, *pwqkvT, *pw1T, *pqkvh, *pvpT, *peh;
    float *pbqkv, *pu;
    cudaGetSymbolAddress((void**)&pxh,    g_xh);
    cudaGetSymbolAddress((void**)&pwqkvT, g_wqkvT);
    cudaGetSymbolAddress((void**)&pw1T,   g_w1T);
    cudaGetSymbolAddress((void**)&pqkvh,  g_qkvh);
    cudaGetSymbolAddress((void**)&pvpT,   g_vpT);
    cudaGetSymbolAddress((void**)&peh,    g_eh);
    cudaGetSymbolAddress((void**)&pbqkv,  g_bqkv);
    cudaGetSymbolAddress((void**)&pu,     g_u);

    cudaFuncSetAttribute(gemm_h<0>, cudaFuncAttributeMaxDynamicSharedMemorySize, SMEM_BYTES);
    cudaFuncSetAttribute(gemm_h<1>, cudaFuncAttributeMaxDynamicSharedMemorySize, SMEM_BYTES);
    cudaFuncSetAttribute(gemm_h<2>, cudaFuncAttributeMaxDynamicSharedMemorySize, SMEM_BYTES);
    cudaFuncSetAttribute(gemm_h<3>, cudaFuncAttributeMaxDynamicSharedMemorySize, SMEM_BYTES);

    const float scale = 1.0f / sqrtf((float)DD);

    // prep
    xprep_h<<<(NN * INDIM / 4 + 255) / 256, 256>>>(x, pxh, NN * INDIM / 4);
    pack_wqkvT<<<(1536 * INDIM + 255) / 256, 256>>>(Wq, Wk, Wv, bq, bk, bv);
    pack_w1T<<<(DHALF * DD + 255) / 256, 256>>>(W1);

    // QKV: x[8192,1024] @ wqkvT[1536,1024]^T + bias -> qkv half
    gemm_h<0><<<dim3(12, 64), NTHR, SMEM_BYTES>>>(
        pxh, INDIM, pwqkvT, INDIM, pqkvh, 1536, 0, INDIM, pbqkv, 1.f);

    // V' = V @ W1, stored transposed: vpT[256][8192]
    gemm_h<3><<<dim3(2, 64), NTHR, SMEM_BYTES>>>(
        pqkvh + 1024, 1536, pw1T, DD, pvpT, 0, 0, DD, nullptr, 1.f);

    // E = exp((Q @ K^T) * scale), half; row sums accumulated atomically
    gemm_h<1><<<dim3(64, 64), NTHR, SMEM_BYTES>>>(
        pqkvh, 1536, pqkvh + 512, 1536, peh, NN, 0, DD, nullptr, scale);

    // U_z = E[:, z*1024:(z+1)*1024] @ vpT[:, z-slice]^T (split-K 8)
    gemm_h<2><<<dim3(2, 64, 8), NTHR, SMEM_BYTES>>>(
        peh, NN, pvpT, NN, pu, DHALF, (size_t)NN * DHALF, 1024, nullptr, 1.f);

    pv_reduce_score<<<NN, 256>>>(b1, W2, b2, out);
}